// round 15
// baseline (speedup 1.0000x reference)
#include <cuda_runtime.h>

// Globalizer: per-point 2x2 rotation over a [64, 4096, 128] f32 stream.
// x:   [B, N, 128] f32 ; R: [B, N, 2, 2] f32 (r00, r01, r10, r11 per point)
// y0 = r00*x0 + r01*x1 ; y1 = r10*x0 + r11*x1 per consecutive pair.
//
// FINAL (14-round sweep, converged): HBM-bound at ~6.0 TB/s DRAM-active
// (~75% of 8 TB/s spec) -- the measured ceiling for a 1:1 interleaved
// read/write stream on this part. ncu dur stable at 36.1-36.5 us across
// six runs of this shape; timed dur 43.5-45.2 us (harness variance).
//
// Winning shape: 256-bit accesses (sm_100+ ld/st.global.v8.f32), exactly
// one 32B chunk (8 floats = 4 rotated pairs) per thread. Lanes hold
// consecutive 32B chunks -> each warp instruction covers 1024B densely
// (8 full 128B lines), halving LSU/L2 request count vs 128-bit (the only
// change that measurably helped: 39.4 -> 36.1 us). 16 consecutive lanes
// share one R load (L1 broadcast). Grid divides the problem exactly
// (4,194,304 chunks = 8192 blocks x 512 threads): no bounds branch.
//
// Measured neutral-or-worse and deliberately absent: cache hints
// (.cs/.nc/.cg x4 null results), per-thread MLP batching (-15% at v4,
// -1% at v8), persistent grids (neutral), cp.async.bulk 32KB tiles (-35%:
// occupancy loss + granularity-insensitive DRAM path).

#define THREADS 512

__global__ __launch_bounds__(THREADS) void rot2_kernel(
    const float* __restrict__ x,
    const float4* __restrict__ R,
    float* __restrict__ out)
{
    int t = blockIdx.x * THREADS + threadIdx.x;

    // 128 floats per point = 16 chunks per point
    float4 r = __ldg(&R[t >> 4]);

    const float* px = x   + ((size_t)t << 3);
    float*       po = out + ((size_t)t << 3);

    float a0, a1, a2, a3, a4, a5, a6, a7;
    asm volatile(
        "ld.global.v8.f32 {%0,%1,%2,%3,%4,%5,%6,%7}, [%8];"
        : "=f"(a0), "=f"(a1), "=f"(a2), "=f"(a3),
          "=f"(a4), "=f"(a5), "=f"(a6), "=f"(a7)
        : "l"(px));

    float o0 = fmaf(r.x, a0, r.y * a1);
    float o1 = fmaf(r.z, a0, r.w * a1);
    float o2 = fmaf(r.x, a2, r.y * a3);
    float o3 = fmaf(r.z, a2, r.w * a3);
    float o4 = fmaf(r.x, a4, r.y * a5);
    float o5 = fmaf(r.z, a4, r.w * a5);
    float o6 = fmaf(r.x, a6, r.y * a7);
    float o7 = fmaf(r.z, a6, r.w * a7);

    asm volatile(
        "st.global.v8.f32 [%0], {%1,%2,%3,%4,%5,%6,%7,%8};"
        :: "l"(po),
           "f"(o0), "f"(o1), "f"(o2), "f"(o3),
           "f"(o4), "f"(o5), "f"(o6), "f"(o7)
        : "memory");
}

extern "C" void kernel_launch(void* const* d_in, const int* in_sizes, int n_in,
                              void* d_out, int out_size)
{
    const float*  x = (const float*)d_in[0];
    const float4* R = (const float4*)d_in[1];
    float* out = (float*)d_out;

    int n8 = out_size / 8;              // 4,194,304 chunks of 8 floats
    int blocks = n8 / THREADS;          // 8192, exact
    rot2_kernel<<<blocks, THREADS>>>(x, R, out);
}